// round 3
// baseline (speedup 1.0000x reference)
#include <cuda_runtime.h>

// Problem constants (shapes fixed by setup_inputs)
#define NMAX 100000
#define EMAX 1250000
#define F 64

// Scratch (allocation-free rule: __device__ globals)
__device__ int   g_deg[NMAX];
__device__ __align__(16) float g_hs[NMAX * F];   // dinv-prescaled features (layer-reused)
__device__ __align__(16) float g_A [NMAX * F];   // aggregation accumulator (layer-reused)
__device__ float g_gsum[F];

// ---------------------------------------------------------------------------
// 1. init: zero degree counts + mean-pool accumulator
__global__ void k_init(int n) {
    int i = blockIdx.x * blockDim.x + threadIdx.x;
    if (i < n) g_deg[i] = 0;
    if (blockIdx.x == 0 && threadIdx.x < F) g_gsum[threadIdx.x] = 0.f;
}

// 2. in-degree count (self-loop added as +1 at use sites)
__global__ void k_deg(const int* __restrict__ dst, int e) {
    for (int i = blockIdx.x * blockDim.x + threadIdx.x; i < e;
         i += gridDim.x * blockDim.x)
        atomicAdd(&g_deg[dst[i]], 1);
}

// 3. layer-1 GEMM: hs = (x @ W1) * dinv ; A = hs (self-loop seed)
__global__ void k_gemm1(const float* __restrict__ x, const float* __restrict__ W1, int n) {
    __shared__ float W1t[F][9];          // W1t[j][k] = W1[k*64 + j], padded row
    for (int t = threadIdx.x; t < F * 8; t += blockDim.x) {
        int k = t >> 6, j = t & 63;
        W1t[j][k] = W1[t];
    }
    __syncthreads();
    int j  = threadIdx.x & 63;
    int nl = threadIdx.x >> 6;
    for (int base = blockIdx.x * 4; base < n; base += gridDim.x * 4) {
        int i = base + nl;
        if (i < n) {
            float dinv = rsqrtf((float)(g_deg[i] + 1));
            const float* xr = x + i * 8;
            float s = 0.f;
            #pragma unroll
            for (int k = 0; k < 8; k++) s += xr[k] * W1t[j][k];
            float v = s * dinv;
            g_hs[i * F + j] = v;
            g_A [i * F + j] = v;
        }
    }
}

// 4. edge scatter: A[dst] += hs[src]
//    One thread per (edge, 4-float chunk): float4 gather + 4 scalar red.add.
__global__ void k_scatter(const int* __restrict__ src, const int* __restrict__ dst, int e) {
    unsigned gid = blockIdx.x * blockDim.x + threadIdx.x;   // e*16 = 20M < 2^31
    unsigned idx = gid >> 4;
    unsigned c   = gid & 15u;
    if (idx < (unsigned)e) {
        int s = src[idx];
        int d = dst[idx];
        float4 v = ((const float4*)g_hs)[(size_t)s * 16 + c];
        float* p = g_A + (size_t)d * F + c * 4;
        atomicAdd(p + 0, v.x);
        atomicAdd(p + 1, v.y);
        atomicAdd(p + 2, v.z);
        atomicAdd(p + 3, v.w);
    }
}

// 5. layer-1 finalize + layer-2 GEMM:
//    h1 = relu(dinv*A + b1);  hs = (h1 @ W2) * dinv;  A = hs
__global__ void k_fin1_gemm2(const float* __restrict__ W2, const float* __restrict__ b1, int n) {
    __shared__ float W2t[F][F + 1];      // W2t[j][k] = W2[k*64 + j], pad to kill conflicts
    __shared__ float h1s[4][F];
    for (int t = threadIdx.x; t < F * F; t += blockDim.x) {
        int k = t >> 6, j = t & 63;
        W2t[j][k] = W2[t];
    }
    __syncthreads();
    int j  = threadIdx.x & 63;
    int nl = threadIdx.x >> 6;
    float bj = b1[j];
    for (int base = blockIdx.x * 4; base < n; base += gridDim.x * 4) {
        int i = base + nl;
        float dinv = 0.f;
        if (i < n) {
            dinv = rsqrtf((float)(g_deg[i] + 1));
            float h = dinv * g_A[i * F + j] + bj;
            h1s[nl][j] = fmaxf(h, 0.f);
        }
        __syncthreads();
        if (i < n) {
            float s = 0.f;
            #pragma unroll
            for (int k = 0; k < F; k++) s += h1s[nl][k] * W2t[j][k];
            float v = s * dinv;
            g_hs[i * F + j] = v;
            g_A [i * F + j] = v;
        }
        __syncthreads();
    }
}

// 6. layer-2 finalize + mean-pool partial sums
__global__ void k_fin2(const float* __restrict__ b2, int n) {
    __shared__ float red[4][F];
    int j  = threadIdx.x & 63;
    int nl = threadIdx.x >> 6;
    float bj = b2[j];
    float acc = 0.f;
    for (int base = blockIdx.x * 4; base < n; base += gridDim.x * 4) {
        int i = base + nl;
        if (i < n) {
            float dinv = rsqrtf((float)(g_deg[i] + 1));
            acc += dinv * g_A[i * F + j] + bj;
        }
    }
    red[nl][j] = acc;
    __syncthreads();
    if (nl == 0) {
        float t = red[0][j] + red[1][j] + red[2][j] + red[3][j];
        atomicAdd(&g_gsum[j], t);
    }
}

// 7. head: g = gsum/n ; s = relu(state@Wm + bm) ; out = [g,s] @ Wc + bc
__global__ void k_final(const float* __restrict__ state, const float* __restrict__ Wm,
                        const float* __restrict__ bm, const float* __restrict__ Wc,
                        const float* __restrict__ bc, float* __restrict__ out, int n) {
    __shared__ float c128[128];
    int j = threadIdx.x;                 // 128 threads
    if (j < 64) {
        c128[j] = g_gsum[j] / (float)n;
    } else {
        int jj = j - 64;
        float s = bm[jj];
        #pragma unroll
        for (int k = 0; k < 8; k++) s += state[k] * Wm[k * 64 + jj];
        c128[j] = fmaxf(s, 0.f);
    }
    __syncthreads();
    if (j < 2) {
        float s = bc[j];
        for (int k = 0; k < 128; k++) s += c128[k] * Wc[k * 2 + j];
        out[j] = s;
    }
}

// ---------------------------------------------------------------------------
extern "C" void kernel_launch(void* const* d_in, const int* in_sizes, int n_in,
                              void* d_out, int out_size) {
    const float* x     = (const float*)d_in[0];
    const float* state = (const float*)d_in[1];
    const float* W1    = (const float*)d_in[2];
    const float* b1    = (const float*)d_in[3];
    const float* W2    = (const float*)d_in[4];
    const float* b2    = (const float*)d_in[5];
    const float* Wm    = (const float*)d_in[6];
    const float* bm    = (const float*)d_in[7];
    const float* Wc    = (const float*)d_in[8];
    const float* bc    = (const float*)d_in[9];
    const int*   ei    = (const int*)d_in[10];
    float* out         = (float*)d_out;

    int n = in_sizes[0] / 8;       // 100000
    int e = in_sizes[10] / 2;      // 1250000
    const int* src = ei;
    const int* dst = ei + e;

    const int T = 256;
    k_init<<<(n + T - 1) / T, T>>>(n);
    k_deg<<<1184, T>>>(dst, e);
    k_gemm1<<<2048, T>>>(x, W1, n);
    k_scatter<<<(e * 16 + T - 1) / T, T>>>(src, dst, e);
    k_fin1_gemm2<<<2048, T>>>(W2, b1, n);
    k_scatter<<<(e * 16 + T - 1) / T, T>>>(src, dst, e);
    k_fin2<<<1024, T>>>(b2, n);
    k_final<<<1, 128>>>(state, Wm, bm, Wc, bc, out, n);
}

// round 4
// speedup vs baseline: 2.4293x; 2.4293x over previous
#include <cuda_runtime.h>

#define NMAX 100000
#define EMAX 1250000
#define F 64
#define SCAN_T 512

// Scratch (__device__ globals; no allocation allowed)
__device__ int   g_deg[NMAX];
__device__ int   g_rowtmp[NMAX];
__device__ int   g_rowptr[NMAX];
__device__ int   g_pos[NMAX];
__device__ int   g_bsum[256];
__device__ int   g_boff[256];
__device__ int   g_csr[EMAX];
__device__ __align__(16) float g_hs [NMAX * F];  // layer-1 dinv-prescaled features
__device__ __align__(16) float g_hs2[NMAX * F];  // layer-2 dinv-prescaled features
__device__ float g_gsum[F];

// ---------------------------------------------------------------------------
__global__ void k_init(int n) {
    int i = blockIdx.x * blockDim.x + threadIdx.x;
    if (i < n) g_deg[i] = 0;
    if (blockIdx.x == 0 && threadIdx.x < F) g_gsum[threadIdx.x] = 0.f;
}

__global__ void k_deg(const int* __restrict__ dst, int e) {
    for (int i = blockIdx.x * blockDim.x + threadIdx.x; i < e;
         i += gridDim.x * blockDim.x)
        atomicAdd(&g_deg[dst[i]], 1);
}

// exclusive scan, pass 1: per-block scan of degrees
__global__ void k_scan1(int n) {
    __shared__ int sm[SCAN_T];
    int tid = threadIdx.x;
    int i = blockIdx.x * SCAN_T + tid;
    int v = (i < n) ? g_deg[i] : 0;
    sm[tid] = v;
    __syncthreads();
    for (int off = 1; off < SCAN_T; off <<= 1) {
        int t = (tid >= off) ? sm[tid - off] : 0;
        __syncthreads();
        sm[tid] += t;
        __syncthreads();
    }
    if (i < n) g_rowtmp[i] = sm[tid] - v;         // exclusive
    if (tid == SCAN_T - 1) g_bsum[blockIdx.x] = sm[tid];
}

// pass 2: scan block sums (nb <= 256)
__global__ void k_scan2(int nb) {
    __shared__ int sm[256];
    int tid = threadIdx.x;
    int v = (tid < nb) ? g_bsum[tid] : 0;
    sm[tid] = v;
    __syncthreads();
    for (int off = 1; off < 256; off <<= 1) {
        int t = (tid >= off) ? sm[tid - off] : 0;
        __syncthreads();
        sm[tid] += t;
        __syncthreads();
    }
    if (tid < nb) g_boff[tid] = sm[tid] - v;      // exclusive
}

// pass 3: combine -> rowptr, and init fill cursor
__global__ void k_scan3(int n) {
    int i = blockIdx.x * blockDim.x + threadIdx.x;
    if (i < n) {
        int rp = g_rowtmp[i] + g_boff[i / SCAN_T];
        g_rowptr[i] = rp;
        g_pos[i] = rp;
    }
}

// CSR fill: bucket sources by destination
__global__ void k_fill(const int* __restrict__ src, const int* __restrict__ dst, int e) {
    for (int i = blockIdx.x * blockDim.x + threadIdx.x; i < e;
         i += gridDim.x * blockDim.x) {
        int slot = atomicAdd(&g_pos[dst[i]], 1);
        g_csr[slot] = src[i];
    }
}

// layer-1 GEMM: hs = (x @ W1) * dinv
__global__ void k_gemm1(const float* __restrict__ x, const float* __restrict__ W1, int n) {
    __shared__ float W1t[F][9];                    // W1t[j][k] = W1[k*64 + j]
    for (int t = threadIdx.x; t < F * 8; t += blockDim.x) {
        int k = t >> 6, j = t & 63;
        W1t[j][k] = W1[t];
    }
    __syncthreads();
    int j  = threadIdx.x & 63;
    int nl = threadIdx.x >> 6;
    for (int base = blockIdx.x * 4; base < n; base += gridDim.x * 4) {
        int i = base + nl;
        if (i < n) {
            float dinv = rsqrtf((float)(g_deg[i] + 1));
            const float* xr = x + i * 8;
            float s = 0.f;
            #pragma unroll
            for (int k = 0; k < 8; k++) s += xr[k] * W1t[j][k];
            g_hs[i * F + j] = s * dinv;
        }
    }
}

// layer-1 gather + finalize + layer-2 GEMM, fused.
// One warp per node; lane owns 2 features. hs2 = (relu(dinv*agg + b1) @ W2) * dinv
__global__ void k_agg1_gemm2(const float* __restrict__ W2, const float* __restrict__ b1, int n) {
    __shared__ float2 W2s[F][32];                  // W2s[k][lane] = (W2[k][2l], W2[k][2l+1])
    __shared__ float h1s[8][F];
    int tid = threadIdx.x;
    for (int t = tid; t < F * 32; t += 256)
        ((float2*)W2s)[t] = ((const float2*)W2)[t];
    __syncthreads();

    int w = tid >> 5, lane = tid & 31;
    int i = blockIdx.x * 8 + w;
    if (i >= n) return;

    const float2* hv = (const float2*)g_hs;
    int rs = g_rowptr[i];
    int d  = g_deg[i];
    float2 acc = hv[(size_t)i * 32 + lane];        // self-loop
    for (int k = 0; k < d; k++) {
        int s = g_csr[rs + k];                     // broadcast across warp
        float2 v = hv[(size_t)s * 32 + lane];
        acc.x += v.x; acc.y += v.y;
    }
    float dinv = rsqrtf((float)(d + 1));
    float2 bb = ((const float2*)b1)[lane];
    h1s[w][2 * lane]     = fmaxf(fmaf(dinv, acc.x, bb.x), 0.f);
    h1s[w][2 * lane + 1] = fmaxf(fmaf(dinv, acc.y, bb.y), 0.f);
    __syncwarp();

    float2 s2 = make_float2(0.f, 0.f);
    #pragma unroll
    for (int k = 0; k < F; k++) {
        float hk = h1s[w][k];
        float2 wr = W2s[k][lane];
        s2.x = fmaf(hk, wr.x, s2.x);
        s2.y = fmaf(hk, wr.y, s2.y);
    }
    ((float2*)g_hs2)[(size_t)i * 32 + lane] = make_float2(s2.x * dinv, s2.y * dinv);
}

// layer-2 gather + finalize + mean-pool partial (b2 folded in at the head)
__global__ void k_agg2(int n) {
    __shared__ float bsum[F];
    int tid = threadIdx.x, w = tid >> 5, lane = tid & 31;
    if (tid < F) bsum[tid] = 0.f;
    __syncthreads();

    const float2* hv = (const float2*)g_hs2;
    float2 accsum = make_float2(0.f, 0.f);
    for (int i = blockIdx.x * 8 + w; i < n; i += gridDim.x * 8) {
        int rs = g_rowptr[i];
        int d  = g_deg[i];
        float2 acc = hv[(size_t)i * 32 + lane];
        for (int k = 0; k < d; k++) {
            int s = g_csr[rs + k];
            float2 v = hv[(size_t)s * 32 + lane];
            acc.x += v.x; acc.y += v.y;
        }
        float dinv = rsqrtf((float)(d + 1));
        accsum.x = fmaf(dinv, acc.x, accsum.x);
        accsum.y = fmaf(dinv, acc.y, accsum.y);
    }
    atomicAdd(&bsum[2 * lane],     accsum.x);
    atomicAdd(&bsum[2 * lane + 1], accsum.y);
    __syncthreads();
    if (tid < F) atomicAdd(&g_gsum[tid], bsum[tid]);
}

// head: g = gsum/n + b2 ; s = relu(state@Wm + bm) ; out = [g,s] @ Wc + bc
__global__ void k_final(const float* __restrict__ state, const float* __restrict__ Wm,
                        const float* __restrict__ bm, const float* __restrict__ Wc,
                        const float* __restrict__ bc, const float* __restrict__ b2,
                        float* __restrict__ out, int n) {
    __shared__ float c128[128];
    int j = threadIdx.x;                           // 128 threads
    if (j < 64) {
        c128[j] = g_gsum[j] / (float)n + b2[j];
    } else {
        int jj = j - 64;
        float s = bm[jj];
        #pragma unroll
        for (int k = 0; k < 8; k++) s += state[k] * Wm[k * 64 + jj];
        c128[j] = fmaxf(s, 0.f);
    }
    __syncthreads();
    if (j < 2) {
        float s = bc[j];
        for (int k = 0; k < 128; k++) s += c128[k] * Wc[k * 2 + j];
        out[j] = s;
    }
}

// ---------------------------------------------------------------------------
extern "C" void kernel_launch(void* const* d_in, const int* in_sizes, int n_in,
                              void* d_out, int out_size) {
    const float* x     = (const float*)d_in[0];
    const float* state = (const float*)d_in[1];
    const float* W1    = (const float*)d_in[2];
    const float* b1    = (const float*)d_in[3];
    const float* W2    = (const float*)d_in[4];
    const float* b2    = (const float*)d_in[5];
    const float* Wm    = (const float*)d_in[6];
    const float* bm    = (const float*)d_in[7];
    const float* Wc    = (const float*)d_in[8];
    const float* bc    = (const float*)d_in[9];
    const int*   ei    = (const int*)d_in[10];
    float* out         = (float*)d_out;

    int n = in_sizes[0] / 8;       // 100000
    int e = in_sizes[10] / 2;      // 1250000
    const int* src = ei;
    const int* dst = ei + e;

    int nb1 = (n + SCAN_T - 1) / SCAN_T;           // 196 <= 256

    const int T = 256;
    k_init<<<(n + T - 1) / T, T>>>(n);
    k_deg<<<1184, T>>>(dst, e);
    k_scan1<<<nb1, SCAN_T>>>(n);
    k_scan2<<<1, 256>>>(nb1);
    k_scan3<<<(n + T - 1) / T, T>>>(n);
    k_fill<<<1184, T>>>(src, dst, e);
    k_gemm1<<<2048, T>>>(x, W1, n);
    k_agg1_gemm2<<<(n + 7) / 8, T>>>(W2, b1, n);
    k_agg2<<<1480, T>>>(n);
    k_final<<<1, 128>>>(state, Wm, bm, Wc, bc, b2, out, n);
}

// round 5
// speedup vs baseline: 2.6626x; 1.0960x over previous
#include <cuda_runtime.h>

#define NMAX 100000
#define EMAX 1250000
#define F 64

// Scratch (__device__ globals; no allocation allowed)
__device__ int   g_deg[NMAX];
__device__ int   g_rowtmp[NMAX];
__device__ int   g_rowptr[NMAX];
__device__ int   g_pos[NMAX];
__device__ float g_dinv[NMAX];
__device__ int   g_bsum[128];
__device__ int   g_boff[128];
__device__ int   g_csr[EMAX];
__device__ __align__(16) float g_hs [NMAX * F];  // layer-1 dinv-prescaled features
__device__ __align__(16) float g_hs2[NMAX * F];  // layer-2 dinv-prescaled features
__device__ float g_gsum[F];

// ---------------------------------------------------------------------------
__global__ void k_init(int n) {
    int i = blockIdx.x * blockDim.x + threadIdx.x;
    if (i < n) g_deg[i] = 0;
    if (blockIdx.x == 0 && threadIdx.x < F) g_gsum[threadIdx.x] = 0.f;
}

__global__ void k_deg(const int* __restrict__ dst, int e) {
    for (int i = blockIdx.x * blockDim.x + threadIdx.x; i < e;
         i += gridDim.x * blockDim.x)
        atomicAdd(&g_deg[dst[i]], 1);
}

// scan pass 1: 1024-thread blocks, shfl warp scans; also emits dinv
__global__ void k_scan1(int n) {
    __shared__ int wsum[32];
    int tid = threadIdx.x, lane = tid & 31, wid = tid >> 5;
    int i = blockIdx.x * 1024 + tid;
    int v = (i < n) ? g_deg[i] : 0;
    int x = v;
    #pragma unroll
    for (int off = 1; off < 32; off <<= 1) {
        int t = __shfl_up_sync(0xffffffffu, x, off);
        if (lane >= off) x += t;
    }
    if (lane == 31) wsum[wid] = x;
    __syncthreads();
    if (wid == 0) {
        int y = wsum[lane];
        #pragma unroll
        for (int off = 1; off < 32; off <<= 1) {
            int t = __shfl_up_sync(0xffffffffu, y, off);
            if (lane >= off) y += t;
        }
        wsum[lane] = y;
    }
    __syncthreads();
    int excl = x - v + (wid > 0 ? wsum[wid - 1] : 0);
    if (i < n) {
        g_rowtmp[i] = excl;
        g_dinv[i] = rsqrtf((float)(v + 1));
    }
    if (tid == 0) g_bsum[blockIdx.x] = wsum[31];
}

// scan pass 2: one 128-thread block over <=128 block sums
__global__ void k_scan2(int nb) {
    __shared__ int wsum[4];
    int tid = threadIdx.x, lane = tid & 31, wid = tid >> 5;
    int v = (tid < nb) ? g_bsum[tid] : 0;
    int x = v;
    #pragma unroll
    for (int off = 1; off < 32; off <<= 1) {
        int t = __shfl_up_sync(0xffffffffu, x, off);
        if (lane >= off) x += t;
    }
    if (lane == 31) wsum[wid] = x;
    __syncthreads();
    int base = 0;
    for (int w = 0; w < wid; w++) base += wsum[w];
    if (tid < nb) g_boff[tid] = base + x - v;    // exclusive
}

// scan pass 3: rowptr = rowtmp + block offset; init fill cursor
__global__ void k_scan3(int n) {
    int i = blockIdx.x * blockDim.x + threadIdx.x;
    if (i < n) {
        int rp = g_rowtmp[i] + g_boff[i >> 10];
        g_rowptr[i] = rp;
        g_pos[i] = rp;
    }
}

// CSR fill: bucket sources by destination
__global__ void k_fill(const int* __restrict__ src, const int* __restrict__ dst, int e) {
    for (int i = blockIdx.x * blockDim.x + threadIdx.x; i < e;
         i += gridDim.x * blockDim.x) {
        int slot = atomicAdd(&g_pos[dst[i]], 1);
        g_csr[slot] = src[i];
    }
}

// layer-1 GEMM: hs = (x @ W1) * dinv
__global__ void k_gemm1(const float* __restrict__ x, const float* __restrict__ W1, int n) {
    __shared__ float W1t[F][9];                    // W1t[j][k] = W1[k*64 + j]
    for (int t = threadIdx.x; t < F * 8; t += blockDim.x) {
        int k = t >> 6, j = t & 63;
        W1t[j][k] = W1[t];
    }
    __syncthreads();
    int j  = threadIdx.x & 63;
    int nl = threadIdx.x >> 6;
    for (int base = blockIdx.x * 4; base < n; base += gridDim.x * 4) {
        int i = base + nl;
        if (i < n) {
            const float* xr = x + i * 8;
            float s = 0.f;
            #pragma unroll
            for (int k = 0; k < 8; k++) s += xr[k] * W1t[j][k];
            g_hs[i * F + j] = s * g_dinv[i];
        }
    }
}

// gather helper: acc += sum of hs rows for node i's in-edges (MLP-4 unrolled)
__device__ __forceinline__ float4 gather_row(const float4* __restrict__ hv,
                                             int rs, int d, int c, float4 acc) {
    int k = 0;
    for (; k + 4 <= d; k += 4) {
        int s0 = g_csr[rs + k], s1 = g_csr[rs + k + 1];
        int s2 = g_csr[rs + k + 2], s3 = g_csr[rs + k + 3];
        float4 v0 = hv[(size_t)s0 * 16 + c];
        float4 v1 = hv[(size_t)s1 * 16 + c];
        float4 v2 = hv[(size_t)s2 * 16 + c];
        float4 v3 = hv[(size_t)s3 * 16 + c];
        acc.x += (v0.x + v1.x) + (v2.x + v3.x);
        acc.y += (v0.y + v1.y) + (v2.y + v3.y);
        acc.z += (v0.z + v1.z) + (v2.z + v3.z);
        acc.w += (v0.w + v1.w) + (v2.w + v3.w);
    }
    for (; k < d; k++) {
        int s = g_csr[rs + k];
        float4 v = hv[(size_t)s * 16 + c];
        acc.x += v.x; acc.y += v.y; acc.z += v.z; acc.w += v.w;
    }
    return acc;
}

// layer-1 gather + finalize + layer-2 GEMM, fused.
// 16 lanes per node, lane c owns float4 features [4c..4c+3].
__global__ void k_agg1_gemm2(const float* __restrict__ W2, const float* __restrict__ b1, int n) {
    __shared__ float4 W2s[F][16];                  // W2s[k][c] = W2[k][4c..4c+3]
    __shared__ float  h1s[16][65];                 // stride 65: kills 2-slot bank conflict
    int tid = threadIdx.x;
    for (int t = tid; t < F * 16; t += 256)
        ((float4*)W2s)[t] = ((const float4*)W2)[t];
    __syncthreads();

    int w = tid >> 5, lane = tid & 31;
    int half = lane >> 4, c = lane & 15;
    int slot = w * 2 + half;
    int i = blockIdx.x * 16 + slot;
    if (i >= n) return;

    const float4* hv = (const float4*)g_hs;
    int rs = g_rowptr[i];
    int d  = g_deg[i];
    float4 acc = hv[(size_t)i * 16 + c];           // self-loop
    acc = gather_row(hv, rs, d, c, acc);

    float dinv = g_dinv[i];
    float4 bb = ((const float4*)b1)[c];
    h1s[slot][4 * c + 0] = fmaxf(fmaf(dinv, acc.x, bb.x), 0.f);
    h1s[slot][4 * c + 1] = fmaxf(fmaf(dinv, acc.y, bb.y), 0.f);
    h1s[slot][4 * c + 2] = fmaxf(fmaf(dinv, acc.z, bb.z), 0.f);
    h1s[slot][4 * c + 3] = fmaxf(fmaf(dinv, acc.w, bb.w), 0.f);
    __syncwarp();

    float4 s2 = make_float4(0.f, 0.f, 0.f, 0.f);
    #pragma unroll
    for (int k = 0; k < F; k++) {
        float hk = h1s[slot][k];
        float4 wr = W2s[k][c];
        s2.x = fmaf(hk, wr.x, s2.x);
        s2.y = fmaf(hk, wr.y, s2.y);
        s2.z = fmaf(hk, wr.z, s2.z);
        s2.w = fmaf(hk, wr.w, s2.w);
    }
    ((float4*)g_hs2)[(size_t)i * 16 + c] =
        make_float4(s2.x * dinv, s2.y * dinv, s2.z * dinv, s2.w * dinv);
}

// layer-2 gather + finalize + mean-pool partial (b2 folded in at the head)
__global__ void k_agg2(int n) {
    __shared__ float bsum[F];
    int tid = threadIdx.x, w = tid >> 5, lane = tid & 31;
    int half = lane >> 4, c = lane & 15;
    if (tid < F) bsum[tid] = 0.f;
    __syncthreads();

    const float4* hv = (const float4*)g_hs2;
    float4 accsum = make_float4(0.f, 0.f, 0.f, 0.f);
    for (int i = blockIdx.x * 16 + w * 2 + half; i < n; i += gridDim.x * 16) {
        int rs = g_rowptr[i];
        int d  = g_deg[i];
        float4 acc = hv[(size_t)i * 16 + c];
        acc = gather_row(hv, rs, d, c, acc);
        float dinv = g_dinv[i];
        accsum.x = fmaf(dinv, acc.x, accsum.x);
        accsum.y = fmaf(dinv, acc.y, accsum.y);
        accsum.z = fmaf(dinv, acc.z, accsum.z);
        accsum.w = fmaf(dinv, acc.w, accsum.w);
    }
    // fold the two half-warps (same features, different nodes)
    accsum.x += __shfl_xor_sync(0xffffffffu, accsum.x, 16);
    accsum.y += __shfl_xor_sync(0xffffffffu, accsum.y, 16);
    accsum.z += __shfl_xor_sync(0xffffffffu, accsum.z, 16);
    accsum.w += __shfl_xor_sync(0xffffffffu, accsum.w, 16);
    if (half == 0) {
        atomicAdd(&bsum[4 * c + 0], accsum.x);
        atomicAdd(&bsum[4 * c + 1], accsum.y);
        atomicAdd(&bsum[4 * c + 2], accsum.z);
        atomicAdd(&bsum[4 * c + 3], accsum.w);
    }
    __syncthreads();
    if (tid < F) atomicAdd(&g_gsum[tid], bsum[tid]);
}

// head: g = gsum/n + b2 ; s = relu(state@Wm + bm) ; out = [g,s] @ Wc + bc
__global__ void k_final(const float* __restrict__ state, const float* __restrict__ Wm,
                        const float* __restrict__ bm, const float* __restrict__ Wc,
                        const float* __restrict__ bc, const float* __restrict__ b2,
                        float* __restrict__ out, int n) {
    __shared__ float c128[128];
    int j = threadIdx.x;                           // 128 threads
    if (j < 64) {
        c128[j] = g_gsum[j] / (float)n + b2[j];
    } else {
        int jj = j - 64;
        float s = bm[jj];
        #pragma unroll
        for (int k = 0; k < 8; k++) s += state[k] * Wm[k * 64 + jj];
        c128[j] = fmaxf(s, 0.f);
    }
    __syncthreads();
    if (j < 2) {
        float s = bc[j];
        for (int k = 0; k < 128; k++) s += c128[k] * Wc[k * 2 + j];
        out[j] = s;
    }
}

// ---------------------------------------------------------------------------
extern "C" void kernel_launch(void* const* d_in, const int* in_sizes, int n_in,
                              void* d_out, int out_size) {
    const float* x     = (const float*)d_in[0];
    const float* state = (const float*)d_in[1];
    const float* W1    = (const float*)d_in[2];
    const float* b1    = (const float*)d_in[3];
    const float* W2    = (const float*)d_in[4];
    const float* b2    = (const float*)d_in[5];
    const float* Wm    = (const float*)d_in[6];
    const float* bm    = (const float*)d_in[7];
    const float* Wc    = (const float*)d_in[8];
    const float* bc    = (const float*)d_in[9];
    const int*   ei    = (const int*)d_in[10];
    float* out         = (float*)d_out;

    int n = in_sizes[0] / 8;       // 100000
    int e = in_sizes[10] / 2;      // 1250000
    const int* src = ei;
    const int* dst = ei + e;

    int nb1 = (n + 1023) / 1024;   // 98 <= 128

    const int T = 256;
    k_init<<<(n + T - 1) / T, T>>>(n);
    k_deg<<<1184, T>>>(dst, e);
    k_scan1<<<nb1, 1024>>>(n);
    k_scan2<<<1, 128>>>(nb1);
    k_scan3<<<(n + T - 1) / T, T>>>(n);
    k_fill<<<1184, T>>>(src, dst, e);
    k_gemm1<<<2048, T>>>(x, W1, n);
    k_agg1_gemm2<<<(n + 15) / 16, T>>>(W2, b1, n);
    k_agg2<<<1480, T>>>(n);
    k_final<<<1, 128>>>(state, Wm, bm, Wc, bc, b2, out, n);
}

// round 6
// speedup vs baseline: 3.1470x; 1.1819x over previous
#include <cuda_runtime.h>
#include <cuda_fp16.h>

#define NMAX 100000
#define EMAX 1250000
#define F 64

// Scratch (__device__ globals; no allocation allowed)
__device__ int   g_deg[NMAX];
__device__ int   g_rowtmp[NMAX];
__device__ int   g_rowptr[NMAX];     // after k_fill: row END (start+deg)
__device__ float g_dinv[NMAX];
__device__ int   g_bsum[128];
__device__ int   g_boff[128];
__device__ int   g_csr[EMAX];
__device__ __align__(16) __half g_hsH [NMAX * F];  // layer-1 dinv-prescaled (fp16)
__device__ __align__(16) __half g_hs2H[NMAX * F];  // layer-2 dinv-prescaled (fp16)
__device__ float g_gsum[F];

// ---------------------------------------------------------------------------
__global__ void k_deg(const int* __restrict__ dst, int e) {
    for (int i = blockIdx.x * blockDim.x + threadIdx.x; i < e;
         i += gridDim.x * blockDim.x)
        atomicAdd(&g_deg[dst[i]], 1);
}

// scan pass 1 (1024 threads, shfl) + dinv + FUSED layer-1 GEMM (fp16 out)
__global__ void k_scan1_gemm1(const float* __restrict__ x, const float* __restrict__ W1, int n) {
    __shared__ int wsum[32];
    __shared__ float W1t[F][12];                   // W1t[j][k], row 48B (16B-aligned)
    int tid = threadIdx.x, lane = tid & 31, wid = tid >> 5;
    if (tid < F * 8) {
        int k = tid >> 6, j = tid & 63;
        W1t[j][k] = W1[tid];
    }
    int i = blockIdx.x * 1024 + tid;
    int v = (i < n) ? g_deg[i] : 0;
    int xsc = v;
    #pragma unroll
    for (int off = 1; off < 32; off <<= 1) {
        int t = __shfl_up_sync(0xffffffffu, xsc, off);
        if (lane >= off) xsc += t;
    }
    if (lane == 31) wsum[wid] = xsc;
    __syncthreads();
    if (wid == 0) {
        int y = wsum[lane];
        #pragma unroll
        for (int off = 1; off < 32; off <<= 1) {
            int t = __shfl_up_sync(0xffffffffu, y, off);
            if (lane >= off) y += t;
        }
        wsum[lane] = y;
    }
    __syncthreads();
    if (i < n) {
        g_rowtmp[i] = xsc - v + (wid > 0 ? wsum[wid - 1] : 0);
        float dinv = rsqrtf((float)(v + 1));
        g_dinv[i] = dinv;
        // fused GEMM1: hs[i][:] = (x[i] @ W1) * dinv, stored fp16
        float4 xa = ((const float4*)x)[i * 2];
        float4 xb = ((const float4*)x)[i * 2 + 1];
        #pragma unroll
        for (int c = 0; c < 8; c++) {
            union { uint4 u; __half2 h[4]; } pk;
            #pragma unroll
            for (int m = 0; m < 4; m++) {
                float s[2];
                #pragma unroll
                for (int t = 0; t < 2; t++) {
                    int j = 8 * c + 2 * m + t;
                    float4 wa = *(const float4*)&W1t[j][0];
                    float4 wb = *(const float4*)&W1t[j][4];
                    s[t] = (xa.x*wa.x + xa.y*wa.y + xa.z*wa.z + xa.w*wa.w
                          + xb.x*wb.x + xb.y*wb.y + xb.z*wb.z + xb.w*wb.w) * dinv;
                }
                pk.h[m] = __floats2half2_rn(s[0], s[1]);
            }
            ((uint4*)g_hsH)[(size_t)i * 8 + c] = pk.u;
        }
    }
    if (tid == 0) g_bsum[blockIdx.x] = wsum[31];
}

// scan pass 2: one 128-thread block over <=128 block sums
__global__ void k_scan2(int nb) {
    __shared__ int wsum[4];
    int tid = threadIdx.x, lane = tid & 31, wid = tid >> 5;
    int v = (tid < nb) ? g_bsum[tid] : 0;
    int xv = v;
    #pragma unroll
    for (int off = 1; off < 32; off <<= 1) {
        int t = __shfl_up_sync(0xffffffffu, xv, off);
        if (lane >= off) xv += t;
    }
    if (lane == 31) wsum[wid] = xv;
    __syncthreads();
    int base = 0;
    for (int w = 0; w < wid; w++) base += wsum[w];
    if (tid < nb) g_boff[tid] = base + xv - v;     // exclusive
}

// scan pass 3: rowptr = rowtmp + block offset (doubles as fill cursor)
__global__ void k_scan3(int n) {
    int i = blockIdx.x * blockDim.x + threadIdx.x;
    if (i < n) g_rowptr[i] = g_rowtmp[i] + g_boff[i >> 10];
}

// CSR fill: advances g_rowptr to row END
__global__ void k_fill(const int* __restrict__ src, const int* __restrict__ dst, int e) {
    for (int i = blockIdx.x * blockDim.x + threadIdx.x; i < e;
         i += gridDim.x * blockDim.x) {
        int slot = atomicAdd(&g_rowptr[dst[i]], 1);
        g_csr[slot] = src[i];
    }
}

// fp16 row-chunk accumulate: 8 halves (uint4) -> 4 float2
__device__ __forceinline__ void acc8(float2 a[4], uint4 v) {
    __half2* h = (__half2*)&v;
    #pragma unroll
    for (int m = 0; m < 4; m++) {
        float2 f = __half22float2(h[m]);
        a[m].x += f.x; a[m].y += f.y;
    }
}

// gather a node's in-edges into fp32 accumulators (8 lanes/node, lane=c)
__device__ __forceinline__ void gather_node(const uint4* __restrict__ hv,
                                            int rs, int d, int c, float2 a[4]) {
    int k = 0;
    for (; k + 4 <= d; k += 4) {
        int s0 = g_csr[rs + k],     s1 = g_csr[rs + k + 1];
        int s2 = g_csr[rs + k + 2], s3 = g_csr[rs + k + 3];
        uint4 v0 = hv[(size_t)s0 * 8 + c];
        uint4 v1 = hv[(size_t)s1 * 8 + c];
        uint4 v2 = hv[(size_t)s2 * 8 + c];
        uint4 v3 = hv[(size_t)s3 * 8 + c];
        acc8(a, v0); acc8(a, v1); acc8(a, v2); acc8(a, v3);
    }
    for (; k < d; k++) {
        uint4 v = hv[(size_t)g_csr[rs + k] * 8 + c];
        acc8(a, v);
    }
}

// layer-1 gather + relu + layer-2 GEMM (register-blocked), 128 nodes/block
__global__ void k_agg1_gemm2(const float* __restrict__ W2, const float* __restrict__ b1, int n) {
    __shared__ float W2s[F][68];                   // [k][j], padded row
    __shared__ float h1s[128][65];
    __shared__ float dvs[128];
    int tid = threadIdx.x;
    for (int t = tid; t < F * F; t += 256) {
        int k = t >> 6, j = t & 63;
        W2s[k][j] = W2[t];
    }

    int w = tid >> 5, lane = tid & 31;
    int grp = lane >> 3, c = lane & 7;
    const uint4* hv = (const uint4*)g_hsH;

    #pragma unroll
    for (int pass = 0; pass < 4; pass++) {
        int nl = pass * 32 + w * 4 + grp;
        int i = blockIdx.x * 128 + nl;
        if (i < n) {
            int re = g_rowptr[i];                  // row end
            int d  = g_deg[i];
            int rs = re - d;
            float2 a[4];
            uint4 sv = hv[(size_t)i * 8 + c];      // self-loop
            {   __half2* h = (__half2*)&sv;
                #pragma unroll
                for (int m = 0; m < 4; m++) a[m] = __half22float2(h[m]); }
            gather_node(hv, rs, d, c, a);
            float dinv = g_dinv[i];
            if (c == 0 && true) dvs[nl] = dinv;
            #pragma unroll
            for (int m = 0; m < 4; m++) {
                float2 bb = ((const float2*)b1)[4 * c + m];
                h1s[nl][8 * c + 2 * m]     = fmaxf(fmaf(dinv, a[m].x, bb.x), 0.f);
                h1s[nl][8 * c + 2 * m + 1] = fmaxf(fmaf(dinv, a[m].y, bb.y), 0.f);
            }
        }
    }
    __syncthreads();

    // GEMM2: thread (q, c2) computes nodes q*4..q*4+3, outputs j=8c2..8c2+7
    int c2 = tid & 7, q = tid >> 3;
    float acc[4][8];
    #pragma unroll
    for (int r = 0; r < 4; r++)
        #pragma unroll
        for (int m = 0; m < 8; m++) acc[r][m] = 0.f;
    #pragma unroll 8
    for (int k = 0; k < F; k++) {
        float4 wa = *(const float4*)&W2s[k][8 * c2];
        float4 wb = *(const float4*)&W2s[k][8 * c2 + 4];
        #pragma unroll
        for (int r = 0; r < 4; r++) {
            float h = h1s[q * 4 + r][k];
            acc[r][0] = fmaf(h, wa.x, acc[r][0]);
            acc[r][1] = fmaf(h, wa.y, acc[r][1]);
            acc[r][2] = fmaf(h, wa.z, acc[r][2]);
            acc[r][3] = fmaf(h, wa.w, acc[r][3]);
            acc[r][4] = fmaf(h, wb.x, acc[r][4]);
            acc[r][5] = fmaf(h, wb.y, acc[r][5]);
            acc[r][6] = fmaf(h, wb.z, acc[r][6]);
            acc[r][7] = fmaf(h, wb.w, acc[r][7]);
        }
    }
    #pragma unroll
    for (int r = 0; r < 4; r++) {
        int nl = q * 4 + r;
        int i = blockIdx.x * 128 + nl;
        if (i < n) {
            float dinv = dvs[nl];
            union { uint4 u; __half2 h[4]; } pk;
            #pragma unroll
            for (int m = 0; m < 4; m++)
                pk.h[m] = __floats2half2_rn(acc[r][2 * m] * dinv, acc[r][2 * m + 1] * dinv);
            ((uint4*)g_hs2H)[(size_t)i * 8 + c2] = pk.u;
        }
    }
}

// layer-2 gather + mean-pool partials (b2 folded at head)
__global__ void k_agg2(int n) {
    __shared__ float bsum[F];
    int tid = threadIdx.x, w = tid >> 5, lane = tid & 31;
    int grp = lane >> 3, c = lane & 7;
    if (tid < F) bsum[tid] = 0.f;
    __syncthreads();

    const uint4* hv = (const uint4*)g_hs2H;
    float2 asum[4] = {{0,0},{0,0},{0,0},{0,0}};
    for (int i = blockIdx.x * 32 + w * 4 + grp; i < n; i += gridDim.x * 32) {
        int re = g_rowptr[i];
        int d  = g_deg[i];
        int rs = re - d;
        float2 a[4];
        uint4 sv = hv[(size_t)i * 8 + c];
        {   __half2* h = (__half2*)&sv;
            #pragma unroll
            for (int m = 0; m < 4; m++) a[m] = __half22float2(h[m]); }
        gather_node(hv, rs, d, c, a);
        float dinv = g_dinv[i];
        #pragma unroll
        for (int m = 0; m < 4; m++) {
            asum[m].x = fmaf(dinv, a[m].x, asum[m].x);
            asum[m].y = fmaf(dinv, a[m].y, asum[m].y);
        }
    }
    // fold the 4 groups (same c, different nodes)
    #pragma unroll
    for (int m = 0; m < 4; m++) {
        asum[m].x += __shfl_xor_sync(0xffffffffu, asum[m].x, 8);
        asum[m].y += __shfl_xor_sync(0xffffffffu, asum[m].y, 8);
        asum[m].x += __shfl_xor_sync(0xffffffffu, asum[m].x, 16);
        asum[m].y += __shfl_xor_sync(0xffffffffu, asum[m].y, 16);
    }
    if (grp == 0) {
        #pragma unroll
        for (int m = 0; m < 4; m++) {
            atomicAdd(&bsum[8 * c + 2 * m],     asum[m].x);
            atomicAdd(&bsum[8 * c + 2 * m + 1], asum[m].y);
        }
    }
    __syncthreads();
    if (tid < F) atomicAdd(&g_gsum[tid], bsum[tid]);
}

// head: g = gsum/n + b2 ; s = relu(state@Wm + bm) ; out = [g,s] @ Wc + bc
__global__ void k_final(const float* __restrict__ state, const float* __restrict__ Wm,
                        const float* __restrict__ bm, const float* __restrict__ Wc,
                        const float* __restrict__ bc, const float* __restrict__ b2,
                        float* __restrict__ out, int n) {
    __shared__ float c128[128];
    int j = threadIdx.x;                           // 128 threads
    if (j < 64) {
        c128[j] = g_gsum[j] / (float)n + b2[j];
    } else {
        int jj = j - 64;
        float s = bm[jj];
        #pragma unroll
        for (int k = 0; k < 8; k++) s += state[k] * Wm[k * 64 + jj];
        c128[j] = fmaxf(s, 0.f);
    }
    __syncthreads();
    if (j < 2) {
        float s = bc[j];
        for (int k = 0; k < 128; k++) s += c128[k] * Wc[k * 2 + j];
        out[j] = s;
    }
}

// ---------------------------------------------------------------------------
extern "C" void kernel_launch(void* const* d_in, const int* in_sizes, int n_in,
                              void* d_out, int out_size) {
    const float* x     = (const float*)d_in[0];
    const float* state = (const float*)d_in[1];
    const float* W1    = (const float*)d_in[2];
    const float* b1    = (const float*)d_in[3];
    const float* W2    = (const float*)d_in[4];
    const float* b2    = (const float*)d_in[5];
    const float* Wm    = (const float*)d_in[6];
    const float* bm    = (const float*)d_in[7];
    const float* Wc    = (const float*)d_in[8];
    const float* bc    = (const float*)d_in[9];
    const int*   ei    = (const int*)d_in[10];
    float* out         = (float*)d_out;

    int n = in_sizes[0] / 8;       // 100000
    int e = in_sizes[10] / 2;      // 1250000
    const int* src = ei;
    const int* dst = ei + e;

    int nb1 = (n + 1023) / 1024;   // 98 <= 128

    void* p_deg = nullptr; void* p_gsum = nullptr;
    cudaGetSymbolAddress(&p_deg, g_deg);
    cudaGetSymbolAddress(&p_gsum, g_gsum);
    cudaMemsetAsync(p_deg, 0, (size_t)n * sizeof(int));
    cudaMemsetAsync(p_gsum, 0, F * sizeof(float));

    const int T = 256;
    k_deg<<<1184, T>>>(dst, e);
    k_scan1_gemm1<<<nb1, 1024>>>(x, W1, n);
    k_scan2<<<1, 128>>>(nb1);
    k_scan3<<<(n + T - 1) / T, T>>>(n);
    k_fill<<<1184, T>>>(src, dst, e);
    k_agg1_gemm2<<<(n + 127) / 128, T>>>(W2, b1, n);
    k_agg2<<<1184, T>>>(n);
    k_final<<<1, 128>>>(state, Wm, bm, Wc, bc, b2, out, n);
}